// round 12
// baseline (speedup 1.0000x reference)
#include <cuda_runtime.h>
#include <cuda_bf16.h>
#include <math.h>
#include <stdint.h>

#define Ltot 4
#define Dm   1024
#define FFd  4096
#define Tt   256
#define Ss   256
#define Nb   16
#define HDh  64
#define TOK  (Tt*Nb)   // 4096 tokens

// ---------------- single scratch arena (256MB) ----------------
__device__ float g_arena[64u * 1024 * 1024];

#define OFF_X    (0)
#define OFF_Q    (4u*1024*1024)
#define OFF_K    (8u*1024*1024)
#define OFF_V    (12u*1024*1024)
#define OFF_P    (20u*1024*1024)
#define OFF_ASHX (40u*1024*1024)
#define OFF_ASHM (44u*1024*1024)
#define OFF_WSH  (48u*1024*1024)
#define OFF_ASHH OFF_Q   // h1 shadow overlays Q..AO (16M words), idle during FFN

// ---------------- small helpers ----------------
__device__ __forceinline__ uint32_t smem_to_u32(const void* p) {
    uint32_t a;
    asm("{ .reg .u64 t; cvta.to.shared.u64 t, %1; cvt.u32.u64 %0, t; }" : "=r"(a) : "l"(p));
    return a;
}
__device__ __forceinline__ uint32_t pack_bf16(float x, float y) {
    __nv_bfloat162 t; t.x = __float2bfloat16(x); t.y = __float2bfloat16(y);
    return *reinterpret_cast<uint32_t*>(&t);
}
__device__ __forceinline__ void split2(float v0, float v1, uint32_t& hi, uint32_t& lo) {
    __nv_bfloat16 h0 = __float2bfloat16(v0);
    __nv_bfloat16 h1 = __float2bfloat16(v1);
    float r0 = v0 - __bfloat162float(h0);
    float r1 = v1 - __bfloat162float(h1);
    __nv_bfloat162 t; t.x = h0; t.y = h1;
    hi = *reinterpret_cast<uint32_t*>(&t);
    lo = pack_bf16(r0, r1);
}
// A-side shadow layout (validated R7..R11)
__device__ __forceinline__ uint32_t shadow_idx(int row, int k, int Ktot) {
    int tile = (row >> 7) * (Ktot >> 5) + (k >> 5);
    int sub = row & 127;
    int ib = sub >> 4, r0 = (sub >> 3) & 1, gg = sub & 7;
    int kk = k & 31;
    int ks = kk >> 4, r1 = (kk & 15) >> 3, tg = (kk & 7) >> 1;
    return (uint32_t)tile * 4096u + (uint32_t)(((((ib * 2 + ks) * 2) * 32) + (gg * 4 + tg)) * 4 + (r1 * 2 + r0));
}
__device__ __forceinline__ void cp16(uint32_t saddr, const void* g) {
    asm volatile("cp.async.cg.shared.global [%0], [%1], 16;" :: "r"(saddr), "l"(g));
}
#define CP_COMMIT() asm volatile("cp.async.commit_group;" ::: "memory")
#define CP_WAIT1()  asm volatile("cp.async.wait_group 1;" ::: "memory")

__device__ __forceinline__ void lds128(uint32_t* r, uint32_t a) {
    asm volatile("ld.shared.v4.b32 {%0,%1,%2,%3},[%4];"
                 : "=r"(r[0]), "=r"(r[1]), "=r"(r[2]), "=r"(r[3]) : "r"(a));
}
__device__ __forceinline__ void mma16(float* c, const uint32_t* a, const uint32_t* b) {
    asm volatile(
        "mma.sync.aligned.m16n8k16.row.col.f32.bf16.bf16.f32 "
        "{%0,%1,%2,%3},{%4,%5,%6,%7},{%8,%9},{%0,%1,%2,%3};\n"
        : "+f"(c[0]), "+f"(c[1]), "+f"(c[2]), "+f"(c[3])
        : "r"(a[0]), "r"(a[1]), "r"(a[2]), "r"(a[3]), "r"(b[0]), "r"(b[1]));
}

// ---------------- copy + split ----------------
__global__ void copy_split_kernel(float4* __restrict__ dst, const float4* __restrict__ src,
                                  uint32_t* __restrict__ sh, int n4) {
    int i = blockIdx.x * blockDim.x + threadIdx.x;
    if (i >= n4) return;
    float4 v = src[i];
    dst[i] = v;
    int row = (i * 4) >> 10;
    int k   = (i * 4) & 1023;
    uint32_t h0, l0, h1, l1;
    split2(v.x, v.y, h0, l0);
    split2(v.z, v.w, h1, l1);
    uint32_t i0 = shadow_idx(row, k, Dm);
    uint32_t i1 = shadow_idx(row, k + 2, Dm);
    sh[i0] = h0; sh[i0 + 128] = l0;
    sh[i1] = h1; sh[i1 + 128] = l1;
}

// ================= weight split: jb-paired fragment-major (validated R11) =================
// word = tile*8192 + ((((jb>>1)*2+ks)*2 + part)*32 + lane)*4 + (jb&1)*2 + r ; lo at +128 words.
// Property: jb 0..15 occupy words [0,4096) of the tile, jb 16..31 occupy [4096,8192)
// -> a 128-wide N sub-tile is a contiguous 4096-word half.
__global__ void wsplit_kernel(const float* __restrict__ W, uint32_t* __restrict__ out, int Nn, int K) {
    int tid = blockIdx.x * blockDim.x + threadIdx.x;
    int total = Nn * (K >> 1);
    if (tid >= total) return;
    int r    = tid & 1;
    int lane = (tid >> 1) & 31;
    int ks   = (tid >> 6) & 1;
    int jb   = (tid >> 7) & 31;
    int tile = tid >> 12;
    int KT = K >> 5;
    int kt = tile % KT, nt = tile / KT;
    int g = lane >> 2, tg = lane & 3;
    int n = nt * 256 + jb * 8 + g;
    int k = kt * 32 + ks * 16 + 2 * tg + r * 8;
    float v0 = W[(size_t)n * K + k];
    float v1 = W[(size_t)n * K + k + 1];
    uint32_t hi, lo;
    split2(v0, v1, hi, lo);
    uint32_t base = (uint32_t)tile * 8192u +
                    (uint32_t)(((((jb >> 1) * 2 + ks) * 2) * 32 + lane) * 4 + (jb & 1) * 2 + r);
    out[base]       = hi;   // part 0
    out[base + 128] = lo;   // part 1
}

// ================= activation split (A-side; only `memory`, once) =================
__global__ void asplit_kernel(const float* __restrict__ A, uint32_t* __restrict__ out, int M, int K) {
    int tid = blockIdx.x * blockDim.x + threadIdx.x;
    int total = M * (K >> 1);
    if (tid >= total) return;
    int r4   = tid & 3;
    int lane = (tid >> 2) & 31;
    int ks   = (tid >> 7) & 1;
    int ib   = (tid >> 8) & 7;
    int tile = tid >> 11;
    int KT = K >> 5;
    int kt = tile % KT, mt = tile / KT;
    int g = lane >> 2, tg = lane & 3;
    int row = mt * 128 + ib * 16 + g + (r4 & 1) * 8;
    int k   = kt * 32 + ks * 16 + 2 * tg + (r4 >> 1) * 8;
    float v0 = A[(size_t)row * K + k];
    float v1 = A[(size_t)row * K + k + 1];
    uint32_t hi, lo;
    split2(v0, v1, hi, lo);
    uint32_t base = (uint32_t)tile * 4096u + ((((ib * 2 + ks) * 2) * 32 + lane) * 4 + r4);
    out[base]       = hi;
    out[base + 128] = lo;
}

// ================= GEMM: tile 128x128, 256 threads, 2 CTAs/SM, 3-stage, 1 sync/slab ========
#define STAGE_BYTES 32768            // A 16KB + B 16KB
#define GEMM_SMEM   (3 * STAGE_BYTES)

__global__ __launch_bounds__(256, 2) void gemm_bf3(
    const uint32_t* __restrict__ Ash, const uint32_t* __restrict__ Bsh,
    const float* __restrict__ bias, float* __restrict__ Cf, uint32_t* __restrict__ Cs,
    int M, int N, int K, float scale, int relu)
{
    extern __shared__ char smem[];
    uint32_t sbase = smem_to_u32(smem);
    int tid = threadIdx.x, lane = tid & 31, wid = tid >> 5;
    int wm = (wid & 3) * 32;         // 4 M-warps
    int wn = (wid >> 2) * 64;        // 2 N-warps
    int g = lane >> 2, tg = lane & 3;
    int KT = K >> 5;
    int nt = blockIdx.x, mt = blockIdx.y;
    const uint32_t* Asrc = Ash + (size_t)mt * KT * 4096;
    // B: shadow tile covers 256 N; this block uses one contiguous 4096-word half.
    const uint32_t* Bsrc = Bsh + ((size_t)(nt >> 1) * KT) * 8192 + (size_t)(nt & 1) * 4096;

    float acc[2][8][4];
#pragma unroll
    for (int i = 0; i < 2; i++)
#pragma unroll
        for (int j = 0; j < 8; j++)
#pragma unroll
            for (int e = 0; e < 4; e++) acc[i][j][e] = 0.f;

    auto issue = [&](int s) {
        uint32_t st = sbase + (uint32_t)(s % 3) * STAGE_BYTES;
        const char* ga = (const char*)(Asrc + (size_t)s * 4096) + tid * 64;
#pragma unroll
        for (int c = 0; c < 4; c++) cp16(st + tid * 64 + c * 16, ga + c * 16);
        const char* gb = (const char*)(Bsrc + (size_t)s * 8192) + tid * 64;
#pragma unroll
        for (int c = 0; c < 4; c++) cp16(st + 16384 + tid * 64 + c * 16, gb + c * 16);
    };

    issue(0); CP_COMMIT();
    issue(1); CP_COMMIT();

    for (int s = 0; s < KT; s++) {
        CP_WAIT1();
        __syncthreads();   // single barrier per slab: data for slab s visible to all;
                           // buffer (s+2)%3 was last read in compute(s-1), before this barrier.
        if (s + 2 < KT) { issue(s + 2); }
        CP_COMMIT();
        uint32_t sA = sbase + (uint32_t)(s % 3) * STAGE_BYTES;
        uint32_t sB = sA + 16384;
#pragma unroll
        for (int ks = 0; ks < 2; ks++) {
            uint32_t aH[2][4], aL[2][4];
#pragma unroll
            for (int i = 0; i < 2; i++) {
                int ib = (wm >> 4) + i;
                uint32_t off = sA + (uint32_t)((((ib * 2 + ks) * 2) * 32 + lane) * 16);
                lds128(aH[i], off);
                lds128(aL[i], off + 512);
            }
#pragma unroll
            for (int jh = 0; jh < 2; jh++) {
                uint32_t bH[4][2], bL[4][2];
#pragma unroll
                for (int p = 0; p < 2; p++) {
                    int jp = (wn >> 4) + jh * 2 + p;
                    uint32_t boff = sB + (uint32_t)((((jp * 2 + ks) * 2) * 32 + lane) * 16);
                    uint32_t th[4], tl[4];
                    lds128(th, boff);
                    lds128(tl, boff + 512);
                    bH[p * 2][0]     = th[0]; bH[p * 2][1]     = th[1];
                    bH[p * 2 + 1][0] = th[2]; bH[p * 2 + 1][1] = th[3];
                    bL[p * 2][0]     = tl[0]; bL[p * 2][1]     = tl[1];
                    bL[p * 2 + 1][0] = tl[2]; bL[p * 2 + 1][1] = tl[3];
                }
#pragma unroll
                for (int i = 0; i < 2; i++)
#pragma unroll
                    for (int j = 0; j < 4; j++) {
                        float* c = acc[i][jh * 4 + j];
                        mma16(c, aH[i], bH[j]);
                        mma16(c, aH[i], bL[j]);
                        mma16(c, aL[i], bH[j]);
                    }
            }
        }
    }

    // epilogue
#pragma unroll
    for (int i = 0; i < 2; i++) {
#pragma unroll
        for (int j = 0; j < 8; j++) {
            int row = mt * 128 + wm + i * 16 + g;
            int col = nt * 128 + wn + j * 8 + tg * 2;
            float b0 = bias[col], b1 = bias[col + 1];
            float v0 = (acc[i][j][0] + b0) * scale;
            float v1 = (acc[i][j][1] + b1) * scale;
            float v2 = (acc[i][j][2] + b0) * scale;
            float v3 = (acc[i][j][3] + b1) * scale;
            if (relu) {
                v0 = fmaxf(v0, 0.f); v1 = fmaxf(v1, 0.f);
                v2 = fmaxf(v2, 0.f); v3 = fmaxf(v3, 0.f);
            }
            if (Cs) {
                uint32_t idx = shadow_idx(row, col, N);
                uint32_t h01, l01, h23, l23;
                split2(v0, v1, h01, l01);
                split2(v2, v3, h23, l23);
                Cs[idx]       = h01;
                Cs[idx + 1]   = h23;
                Cs[idx + 128] = l01;
                Cs[idx + 129] = l23;
            } else {
                *(float2*)(Cf + (size_t)row * N + col)       = make_float2(v0, v1);
                *(float2*)(Cf + (size_t)(row + 8) * N + col) = make_float2(v2, v3);
            }
        }
    }
}

// ================= attention (unchanged) =================
#define AKS 0
#define AVS (256*66)
#define AQ  (2*256*66)
#define AP  (AQ + 8*4*64)
#define ATTN_SMEM ((AP + 8*256*4) * 4)

__global__ __launch_bounds__(256, 1) void attn_kernel(
    const float* __restrict__ Q, const float* __restrict__ K,
    const float* __restrict__ V, uint32_t* __restrict__ OutS, int causal)
{
    extern __shared__ float sm[];
    float* Ks = sm + AKS;
    float* Vs = sm + AVS;
    float* qs = sm + AQ;
    float* ps = sm + AP;

    int tid = threadIdx.x;
    int lane = tid & 31, wrp = tid >> 5;
    int n = blockIdx.x & (Nb - 1);
    int h = blockIdx.x >> 4;
    int bc = h * HDh;

    for (int i = tid; i < 4096; i += 256) {
        int s = i >> 4;
        int d4 = (i & 15) * 4;
        float4 kv = *(const float4*)(K + (size_t)(s * Nb + n) * Dm + bc + d4);
        float4 vv = *(const float4*)(V + (size_t)(s * Nb + n) * Dm + bc + d4);
        float* kd = &Ks[s * 66 + d4];
        float* vd = &Vs[s * 66 + d4];
        kd[0] = kv.x; kd[1] = kv.y; kd[2] = kv.z; kd[3] = kv.w;
        vd[0] = vv.x; vd[1] = vv.y; vd[2] = vv.z; vd[3] = vv.w;
    }
    __syncthreads();

    float* qw = qs + wrp * 4 * 64;
    float* pw = ps + wrp * 256 * 4;

    for (int it = 0; it < 8; it++) {
        int tbase = (it * 8 + wrp) * 4;
#pragma unroll
        for (int tt = 0; tt < 4; tt++) {
            float2 q2 = *(const float2*)(Q + (size_t)((tbase + tt) * Nb + n) * Dm + bc + 2 * lane);
            *(float2*)&qw[tt * 64 + 2 * lane] = q2;
        }
        __syncwarp();

        float sc[4][8];
#pragma unroll
        for (int tt = 0; tt < 4; tt++)
#pragma unroll
            for (int j = 0; j < 8; j++) sc[tt][j] = 0.f;

        for (int d2 = 0; d2 < 32; d2++) {
            float2 q2[4];
#pragma unroll
            for (int tt = 0; tt < 4; tt++) q2[tt] = *(const float2*)&qw[tt * 64 + 2 * d2];
#pragma unroll
            for (int j = 0; j < 8; j++) {
                float2 k2 = *(const float2*)&Ks[(j * 32 + lane) * 66 + 2 * d2];
#pragma unroll
                for (int tt = 0; tt < 4; tt++)
                    sc[tt][j] += q2[tt].x * k2.x + q2[tt].y * k2.y;
            }
        }

        float denom[4];
#pragma unroll
        for (int tt = 0; tt < 4; tt++) {
            int t = tbase + tt;
            if (causal) {
#pragma unroll
                for (int j = 0; j < 8; j++)
                    if (j * 32 + lane > t) sc[tt][j] = -1e9f;
            }
            float m = sc[tt][0];
#pragma unroll
            for (int j = 1; j < 8; j++) m = fmaxf(m, sc[tt][j]);
#pragma unroll
            for (int off = 16; off; off >>= 1) m = fmaxf(m, __shfl_xor_sync(0xffffffffu, m, off));
            float sum = 0.f;
#pragma unroll
            for (int j = 0; j < 8; j++) {
                float e = __expf(sc[tt][j] - m);
                sc[tt][j] = e;
                sum += e;
            }
#pragma unroll
            for (int off = 16; off; off >>= 1) sum += __shfl_xor_sync(0xffffffffu, sum, off);
            denom[tt] = sum;
#pragma unroll
            for (int j = 0; j < 8; j++) pw[(j * 32 + lane) * 4 + tt] = sc[tt][j];
        }
        __syncwarp();

        float2 acc[4];
#pragma unroll
        for (int tt = 0; tt < 4; tt++) acc[tt] = make_float2(0.f, 0.f);
#pragma unroll 4
        for (int s = 0; s < 256; s++) {
            float2 v2 = *(const float2*)&Vs[s * 66 + 2 * lane];
            float4 p4 = *(const float4*)&pw[s * 4];
            acc[0].x += p4.x * v2.x; acc[0].y += p4.x * v2.y;
            acc[1].x += p4.y * v2.x; acc[1].y += p4.y * v2.y;
            acc[2].x += p4.z * v2.x; acc[2].y += p4.z * v2.y;
            acc[3].x += p4.w * v2.x; acc[3].y += p4.w * v2.y;
        }
        int kcol = bc + 2 * lane;
#pragma unroll
        for (int tt = 0; tt < 4; tt++) {
            float inv = 1.f / denom[tt];
            uint32_t hi, lo;
            split2(acc[tt].x * inv, acc[tt].y * inv, hi, lo);
            uint32_t idx = shadow_idx((tbase + tt) * Nb + n, kcol, Dm);
            OutS[idx]       = hi;
            OutS[idx + 128] = lo;
        }
        __syncwarp();
    }
}

// ---------------- LayerNorm (+ residual) with optional split shadow output ----------------
__global__ void ln_kernel(const float* __restrict__ a, const float* __restrict__ r,
                          const float* __restrict__ g, const float* __restrict__ b,
                          float* __restrict__ out, uint32_t* __restrict__ sh)
{
    int row = blockIdx.x, tid = threadIdx.x;
    const float* ar = a + (size_t)row * Dm;
    const float* rr = r ? r + (size_t)row * Dm : nullptr;
    int e0 = 2 * tid;
    int e1 = 512 + 2 * tid;
    float2 p0 = *(const float2*)(ar + e0);
    float2 p1 = *(const float2*)(ar + e1);
    if (rr) {
        float2 r0 = *(const float2*)(rr + e0);
        float2 r1 = *(const float2*)(rr + e1);
        p0.x += r0.x; p0.y += r0.y;
        p1.x += r1.x; p1.y += r1.y;
    }
    float s = p0.x + p0.y + p1.x + p1.y;
    float s2 = p0.x * p0.x + p0.y * p0.y + p1.x * p1.x + p1.y * p1.y;
#pragma unroll
    for (int off = 16; off; off >>= 1) {
        s  += __shfl_down_sync(0xffffffffu, s, off);
        s2 += __shfl_down_sync(0xffffffffu, s2, off);
    }
    __shared__ float ws[8], ws2[8];
    __shared__ float mean_s, rstd_s;
    int w = tid >> 5, lane = tid & 31;
    if (!lane) { ws[w] = s; ws2[w] = s2; }
    __syncthreads();
    if (tid == 0) {
        float S = 0.f, S2 = 0.f;
        for (int i = 0; i < 8; i++) { S += ws[i]; S2 += ws2[i]; }
        float mean = S / Dm;
        float var = S2 / Dm - mean * mean;
        mean_s = mean;
        rstd_s = rsqrtf(var + 1e-5f);
    }
    __syncthreads();
    float mean = mean_s, rstd = rstd_s;
    float o00 = (p0.x - mean) * rstd * g[e0]     + b[e0];
    float o01 = (p0.y - mean) * rstd * g[e0 + 1] + b[e0 + 1];
    float o10 = (p1.x - mean) * rstd * g[e1]     + b[e1];
    float o11 = (p1.y - mean) * rstd * g[e1 + 1] + b[e1 + 1];
    *(float2*)(out + (size_t)row * Dm + e0) = make_float2(o00, o01);
    *(float2*)(out + (size_t)row * Dm + e1) = make_float2(o10, o11);
    if (sh) {
        uint32_t hi, lo;
        split2(o00, o01, hi, lo);
        uint32_t i0 = shadow_idx(row, e0, Dm);
        sh[i0] = hi; sh[i0 + 128] = lo;
        split2(o10, o11, hi, lo);
        uint32_t i1 = shadow_idx(row, e1, Dm);
        sh[i1] = hi; sh[i1 + 128] = lo;
    }
}

// ---------------- host ----------------
extern "C" void kernel_launch(void* const* d_in, const int* in_sizes, int n_in,
                              void* d_out, int out_size)
{
    const float* tgt    = (const float*)d_in[0];
    const float* memory = (const float*)d_in[1];

    bool grouped = (in_sizes[3] == Ltot * Dm * Dm);
    const float *sa_w[4], *sa_b[4], *ca_w[4], *ca_b[4];
    if (grouped) {
        for (int j = 0; j < 4; j++) {
            sa_w[j] = (const float*)d_in[2 + j];
            sa_b[j] = (const float*)d_in[6 + j];
            ca_w[j] = (const float*)d_in[10 + j];
            ca_b[j] = (const float*)d_in[14 + j];
        }
    } else {
        for (int j = 0; j < 4; j++) {
            sa_w[j] = (const float*)d_in[2 + 2 * j];
            sa_b[j] = (const float*)d_in[3 + 2 * j];
            ca_w[j] = (const float*)d_in[10 + 2 * j];
            ca_b[j] = (const float*)d_in[11 + 2 * j];
        }
    }
    const float* w1   = (const float*)d_in[18];
    const float* b1   = (const float*)d_in[19];
    const float* w2   = (const float*)d_in[20];
    const float* b2   = (const float*)d_in[21];
    const float* ln1g = (const float*)d_in[22];
    const float* ln1b = (const float*)d_in[23];
    const float* ln2g = (const float*)d_in[24];
    const float* ln2b = (const float*)d_in[25];
    const float* ln3g = (const float*)d_in[26];
    const float* ln3b = (const float*)d_in[27];
    const float* lnfg = (const float*)d_in[28];
    const float* lnfb = (const float*)d_in[29];

    float* arena;
    cudaGetSymbolAddress((void**)&arena, g_arena);
    float* px  = arena + OFF_X;
    float* pq  = arena + OFF_Q;
    float* pk  = arena + OFF_K;
    float* pv  = arena + OFF_V;
    float* pp  = arena + OFF_P;
    uint32_t* pax = (uint32_t*)arena + OFF_ASHX;
    uint32_t* pam = (uint32_t*)arena + OFF_ASHM;
    uint32_t* pah = (uint32_t*)arena + OFF_ASHH;
    uint32_t* pws = (uint32_t*)arena + OFF_WSH;

    cudaFuncSetAttribute(gemm_bf3, cudaFuncAttributeMaxDynamicSharedMemorySize, GEMM_SMEM);
    cudaFuncSetAttribute(attn_kernel, cudaFuncAttributeMaxDynamicSharedMemorySize, ATTN_SMEM);

    const uint32_t WS_SA = 0;
    const uint32_t WS_CA = 4u*1024*1024;
    const uint32_t WS_W1 = 8u*1024*1024;
    const uint32_t WS_W2 = 12u*1024*1024;
    const size_t SZ_DD = (size_t)Dm * Dm;

    auto wsplit = [&](const float* W, uint32_t* out, int Nn, int K) {
        int total = Nn * (K >> 1);
        wsplit_kernel<<<(total + 255) / 256, 256>>>(W, out, Nn, K);
    };
    auto gemm = [&](const uint32_t* Ash, const uint32_t* Bsh, const float* bias,
                    float* Cf, uint32_t* Cs, int M, int N, int K, float scale, int relu) {
        dim3 grid(N / 128, M / 128);
        gemm_bf3<<<grid, 256, GEMM_SMEM>>>(Ash, Bsh, bias, Cf, Cs, M, N, K, scale, relu);
    };

    // launch 1: memory shadow; launch 2: x copy+split
    {
        int total = TOK * (Dm >> 1);
        asplit_kernel<<<(total + 255) / 256, 256>>>(memory, pam, TOK, Dm);
    }
    {
        int n4 = TOK * Dm / 4;
        copy_split_kernel<<<(n4 + 255) / 256, 256>>>((float4*)px, (const float4*)tgt, pax, n4);
    }

    const float qscale = 0.125f;  // 64^-0.5

    for (int l = 0; l < Ltot; l++) {
        size_t bo = (size_t)l * Dm;

        // ---- self-attention (causal) ----
        // interleave wsplit/gemm so (l=0) launch #6 (1-indexed) is a DD gemm (ncu -s 5 -c 1).
        wsplit(sa_w[0] + (size_t)l * SZ_DD, pws + WS_SA + 0 * SZ_DD, Dm, Dm);        // 3
        gemm(pax, pws + WS_SA + 0 * SZ_DD, sa_b[0] + bo, pq, nullptr, TOK, Dm, Dm, qscale, 0); // 4
        wsplit(sa_w[1] + (size_t)l * SZ_DD, pws + WS_SA + 1 * SZ_DD, Dm, Dm);        // 5
        gemm(pax, pws + WS_SA + 1 * SZ_DD, sa_b[1] + bo, pk, nullptr, TOK, Dm, Dm, 1.f, 0);    // 6 <- captured
        wsplit(sa_w[2] + (size_t)l * SZ_DD, pws + WS_SA + 2 * SZ_DD, Dm, Dm);
        gemm(pax, pws + WS_SA + 2 * SZ_DD, sa_b[2] + bo, pv, nullptr, TOK, Dm, Dm, 1.f, 0);
        attn_kernel<<<Nb * 16, 256, ATTN_SMEM>>>(pq, pk, pv, pax, 1);
        wsplit(sa_w[3] + (size_t)l * SZ_DD, pws + WS_SA + 3 * SZ_DD, Dm, Dm);
        gemm(pax, pws + WS_SA + 3 * SZ_DD, sa_b[3] + bo, pp, nullptr, TOK, Dm, Dm, 1.f, 0);
        ln_kernel<<<TOK, 256>>>(px, pp, ln1g + bo, ln1b + bo, px, pax);

        // ---- cross-attention ----
        wsplit(ca_w[0] + (size_t)l * SZ_DD, pws + WS_CA + 0 * SZ_DD, Dm, Dm);
        gemm(pax, pws + WS_CA + 0 * SZ_DD, ca_b[0] + bo, pq, nullptr, TOK, Dm, Dm, qscale, 0);
        wsplit(ca_w[1] + (size_t)l * SZ_DD, pws + WS_CA + 1 * SZ_DD, Dm, Dm);
        gemm(pam, pws + WS_CA + 1 * SZ_DD, ca_b[1] + bo, pk, nullptr, TOK, Dm, Dm, 1.f, 0);
        wsplit(ca_w[2] + (size_t)l * SZ_DD, pws + WS_CA + 2 * SZ_DD, Dm, Dm);
        gemm(pam, pws + WS_CA + 2 * SZ_DD, ca_b[2] + bo, pv, nullptr, TOK, Dm, Dm, 1.f, 0);
        attn_kernel<<<Nb * 16, 256, ATTN_SMEM>>>(pq, pk, pv, pax, 0);
        wsplit(ca_w[3] + (size_t)l * SZ_DD, pws + WS_CA + 3 * SZ_DD, Dm, Dm);
        gemm(pax, pws + WS_CA + 3 * SZ_DD, ca_b[3] + bo, pp, nullptr, TOK, Dm, Dm, 1.f, 0);
        ln_kernel<<<TOK, 256>>>(px, pp, ln2g + bo, ln2b + bo, px, pax);

        // ---- FFN ----
        wsplit(w1 + (size_t)l * FFd * Dm, pws + WS_W1, FFd, Dm);
        gemm(pax, pws + WS_W1, b1 + (size_t)l * FFd, nullptr, pah, TOK, FFd, Dm, 1.f, 1);
        wsplit(w2 + (size_t)l * Dm * FFd, pws + WS_W2, Dm, FFd);
        gemm(pah, pws + WS_W2, b2 + bo, pp, nullptr, TOK, Dm, FFd, 1.f, 0);
        ln_kernel<<<TOK, 256>>>(px, pp, ln3g + bo, ln3b + bo, px, pax);
    }

    ln_kernel<<<TOK, 256>>>(px, nullptr, lnfg, lnfb, (float*)d_out, nullptr);
}

// round 14
// speedup vs baseline: 1.0137x; 1.0137x over previous
#include <cuda_runtime.h>
#include <cuda_bf16.h>
#include <math.h>
#include <stdint.h>

#define Ltot 4
#define Dm   1024
#define FFd  4096
#define Tt   256
#define Ss   256
#define Nb   16
#define HDh  64
#define TOK  (Tt*Nb)   // 4096 tokens

// ---------------- single scratch arena (256MB) ----------------
//   X    0..4M     activations f32
//   QKV  4M..16M   fused q|k|v f32, row stride 3072
//   P    20M..24M  pre-LN gemm output f32
//   ASHH 4M..20M   h1 shadow overlay (16M words), FFN only (QKV dead then)
//   ASHX 40M..44M  activation shadow
//   ASHM 44M..48M  memory shadow
//   WSH  48M..64M  per-layer weight shadows
__device__ float g_arena[64u * 1024 * 1024];

#define OFF_X    (0)
#define OFF_QKV  (4u*1024*1024)
#define OFF_P    (20u*1024*1024)
#define OFF_ASHX (40u*1024*1024)
#define OFF_ASHM (44u*1024*1024)
#define OFF_WSH  (48u*1024*1024)
#define OFF_ASHH OFF_QKV
#define QKVS 3072

// ---------------- small helpers ----------------
__device__ __forceinline__ uint32_t smem_to_u32(const void* p) {
    uint32_t a;
    asm("{ .reg .u64 t; cvta.to.shared.u64 t, %1; cvt.u32.u64 %0, t; }" : "=r"(a) : "l"(p));
    return a;
}
__device__ __forceinline__ uint32_t pack_bf16(float x, float y) {
    __nv_bfloat162 t; t.x = __float2bfloat16(x); t.y = __float2bfloat16(y);
    return *reinterpret_cast<uint32_t*>(&t);
}
__device__ __forceinline__ void split2(float v0, float v1, uint32_t& hi, uint32_t& lo) {
    __nv_bfloat16 h0 = __float2bfloat16(v0);
    __nv_bfloat16 h1 = __float2bfloat16(v1);
    float r0 = v0 - __bfloat162float(h0);
    float r1 = v1 - __bfloat162float(h1);
    __nv_bfloat162 t; t.x = h0; t.y = h1;
    hi = *reinterpret_cast<uint32_t*>(&t);
    lo = pack_bf16(r0, r1);
}
// A-side shadow layout (validated R7..R12)
__device__ __forceinline__ uint32_t shadow_idx(int row, int k, int Ktot) {
    int tile = (row >> 7) * (Ktot >> 5) + (k >> 5);
    int sub = row & 127;
    int ib = sub >> 4, r0 = (sub >> 3) & 1, gg = sub & 7;
    int kk = k & 31;
    int ks = kk >> 4, r1 = (kk & 15) >> 3, tg = (kk & 7) >> 1;
    return (uint32_t)tile * 4096u + (uint32_t)(((((ib * 2 + ks) * 2) * 32) + (gg * 4 + tg)) * 4 + (r1 * 2 + r0));
}
__device__ __forceinline__ void cp16(uint32_t saddr, const void* g) {
    asm volatile("cp.async.cg.shared.global [%0], [%1], 16;" :: "r"(saddr), "l"(g));
}
#define CP_COMMIT() asm volatile("cp.async.commit_group;" ::: "memory")
#define CP_WAIT1()  asm volatile("cp.async.wait_group 1;" ::: "memory")

__device__ __forceinline__ void lds128(uint32_t* r, uint32_t a) {
    asm volatile("ld.shared.v4.b32 {%0,%1,%2,%3},[%4];"
                 : "=r"(r[0]), "=r"(r[1]), "=r"(r[2]), "=r"(r[3]) : "r"(a));
}
__device__ __forceinline__ void mma16(float* c, const uint32_t* a, const uint32_t* b) {
    asm volatile(
        "mma.sync.aligned.m16n8k16.row.col.f32.bf16.bf16.f32 "
        "{%0,%1,%2,%3},{%4,%5,%6,%7},{%8,%9},{%0,%1,%2,%3};\n"
        : "+f"(c[0]), "+f"(c[1]), "+f"(c[2]), "+f"(c[3])
        : "r"(a[0]), "r"(a[1]), "r"(a[2]), "r"(a[3]), "r"(b[0]), "r"(b[1]));
}

// ---------------- copy + split ----------------
__global__ void copy_split_kernel(float4* __restrict__ dst, const float4* __restrict__ src,
                                  uint32_t* __restrict__ sh, int n4) {
    int i = blockIdx.x * blockDim.x + threadIdx.x;
    if (i >= n4) return;
    float4 v = src[i];
    dst[i] = v;
    int row = (i * 4) >> 10;
    int k   = (i * 4) & 1023;
    uint32_t h0, l0, h1, l1;
    split2(v.x, v.y, h0, l0);
    split2(v.z, v.w, h1, l1);
    uint32_t i0 = shadow_idx(row, k, Dm);
    uint32_t i1 = shadow_idx(row, k + 2, Dm);
    sh[i0] = h0; sh[i0 + 128] = l0;
    sh[i1] = h1; sh[i1 + 128] = l1;
}

// ================= weight split: jb-paired fragment-major (validated R11) =================
// word = tile*8192 + ((((jb>>1)*2+ks)*2 + part)*32 + lane)*4 + (jb&1)*2 + r ; lo at +128 words.
// Contiguity: a 1024-wide weight's shadow = 4 nt-tiles = 1M words, so adjacent weight slots
// concatenate into a valid wider-N shadow (used by the fused QKV / KV gemms).
__global__ void wsplit_kernel(const float* __restrict__ W, uint32_t* __restrict__ out, int Nn, int K) {
    int tid = blockIdx.x * blockDim.x + threadIdx.x;
    int total = Nn * (K >> 1);
    if (tid >= total) return;
    int r    = tid & 1;
    int lane = (tid >> 1) & 31;
    int ks   = (tid >> 6) & 1;
    int jb   = (tid >> 7) & 31;
    int tile = tid >> 12;
    int KT = K >> 5;
    int kt = tile % KT, nt = tile / KT;
    int g = lane >> 2, tg = lane & 3;
    int n = nt * 256 + jb * 8 + g;
    int k = kt * 32 + ks * 16 + 2 * tg + r * 8;
    float v0 = W[(size_t)n * K + k];
    float v1 = W[(size_t)n * K + k + 1];
    uint32_t hi, lo;
    split2(v0, v1, hi, lo);
    uint32_t base = (uint32_t)tile * 8192u +
                    (uint32_t)(((((jb >> 1) * 2 + ks) * 2) * 32 + lane) * 4 + (jb & 1) * 2 + r);
    out[base]       = hi;   // part 0
    out[base + 128] = lo;   // part 1
}

// ================= activation split (A-side; only `memory`, once) =================
__global__ void asplit_kernel(const float* __restrict__ A, uint32_t* __restrict__ out, int M, int K) {
    int tid = blockIdx.x * blockDim.x + threadIdx.x;
    int total = M * (K >> 1);
    if (tid >= total) return;
    int r4   = tid & 3;
    int lane = (tid >> 2) & 31;
    int ks   = (tid >> 7) & 1;
    int ib   = (tid >> 8) & 7;
    int tile = tid >> 11;
    int KT = K >> 5;
    int kt = tile % KT, mt = tile / KT;
    int g = lane >> 2, tg = lane & 3;
    int row = mt * 128 + ib * 16 + g + (r4 & 1) * 8;
    int k   = kt * 32 + ks * 16 + 2 * tg + (r4 >> 1) * 8;
    float v0 = A[(size_t)row * K + k];
    float v1 = A[(size_t)row * K + k + 1];
    uint32_t hi, lo;
    split2(v0, v1, hi, lo);
    uint32_t base = (uint32_t)tile * 4096u + ((((ib * 2 + ks) * 2) * 32 + lane) * 4 + r4);
    out[base]       = hi;
    out[base + 128] = lo;
}

// ================= GEMM: R11-exact mainloop; epilogue gains ldc + segmented bias ============
// C[M,N] (row stride ldc) = op((A@B^T + bias)*scale). seg3: bias/scale per 1024-col segment
// (segment 0 gets `scale`, others 1.0; bias pointers b0/b1/b2 per segment).
#define STAGE_BYTES 49152
#define GEMM_SMEM   (3 * STAGE_BYTES)

__global__ __launch_bounds__(512, 1) void gemm_bf3(
    const uint32_t* __restrict__ Ash, const uint32_t* __restrict__ Bsh,
    const float* __restrict__ b0p, const float* __restrict__ b1p, const float* __restrict__ b2p,
    int seg3, float* __restrict__ Cf, uint32_t* __restrict__ Cs,
    int M, int N, int ldc, int K, float scale, int relu)
{
    extern __shared__ char smem[];
    uint32_t sbase = smem_to_u32(smem);
    int tid = threadIdx.x, lane = tid & 31, wid = tid >> 5;
    int wm = (wid & 3) * 32;         // 4 M-warps
    int wn = (wid >> 2) * 64;        // 4 N-warps
    int g = lane >> 2, tg = lane & 3;
    int KT = K >> 5;
    int nt = blockIdx.x, mt = blockIdx.y;
    const uint32_t* Asrc = Ash + (size_t)mt * KT * 4096;
    const uint32_t* Bsrc = Bsh + (size_t)nt * KT * 8192;

    float acc[2][8][4];
#pragma unroll
    for (int i = 0; i < 2; i++)
#pragma unroll
        for (int j = 0; j < 8; j++)
#pragma unroll
            for (int e = 0; e < 4; e++) acc[i][j][e] = 0.f;

    auto issue = [&](int s) {
        uint32_t st = sbase + (uint32_t)(s % 3) * STAGE_BYTES;
        const char* ga = (const char*)(Asrc + (size_t)s * 4096) + tid * 32;
#pragma unroll
        for (int c = 0; c < 2; c++) cp16(st + tid * 32 + c * 16, ga + c * 16);
        const char* gb = (const char*)(Bsrc + (size_t)s * 8192) + tid * 64;
#pragma unroll
        for (int c = 0; c < 4; c++) cp16(st + 16384 + tid * 64 + c * 16, gb + c * 16);
    };

    issue(0); CP_COMMIT();
    if (KT > 1) issue(1);
    CP_COMMIT();

    for (int s = 0; s < KT; s++) {
        CP_WAIT1();
        __syncthreads();
        uint32_t sA = sbase + (uint32_t)(s % 3) * STAGE_BYTES;
        uint32_t sB = sA + 16384;
#pragma unroll
        for (int ks = 0; ks < 2; ks++) {
            uint32_t aH[2][4], aL[2][4];
#pragma unroll
            for (int i = 0; i < 2; i++) {
                int ib = (wm >> 4) + i;
                uint32_t off = sA + (uint32_t)((((ib * 2 + ks) * 2) * 32 + lane) * 16);
                lds128(aH[i], off);
                lds128(aL[i], off + 512);
            }
#pragma unroll
            for (int jh = 0; jh < 2; jh++) {
                uint32_t bH[4][2], bL[4][2];
#pragma unroll
                for (int p = 0; p < 2; p++) {
                    int jp = (wn >> 4) + jh * 2 + p;
                    uint32_t boff = sB + (uint32_t)((((jp * 2 + ks) * 2) * 32 + lane) * 16);
                    uint32_t th[4], tl[4];
                    lds128(th, boff);
                    lds128(tl, boff + 512);
                    bH[p * 2][0]     = th[0]; bH[p * 2][1]     = th[1];
                    bH[p * 2 + 1][0] = th[2]; bH[p * 2 + 1][1] = th[3];
                    bL[p * 2][0]     = tl[0]; bL[p * 2][1]     = tl[1];
                    bL[p * 2 + 1][0] = tl[2]; bL[p * 2 + 1][1] = tl[3];
                }
#pragma unroll
                for (int i = 0; i < 2; i++)
#pragma unroll
                    for (int j = 0; j < 4; j++) {
                        float* c = acc[i][jh * 4 + j];
                        mma16(c, aH[i], bH[j]);
                        mma16(c, aH[i], bL[j]);
                        mma16(c, aL[i], bH[j]);
                    }
            }
        }
        __syncthreads();
        if (s + 2 < KT) issue(s + 2);
        CP_COMMIT();
    }

    // epilogue
#pragma unroll
    for (int i = 0; i < 2; i++) {
#pragma unroll
        for (int j = 0; j < 8; j++) {
            int row = mt * 128 + wm + i * 16 + g;
            int col = nt * 256 + wn + j * 8 + tg * 2;
            const float* bp;
            float scl;
            int cl;
            if (seg3) {
                int sgi = col >> 10;
                bp = (sgi == 0) ? b0p : ((sgi == 1) ? b1p : b2p);
                scl = (sgi == 0) ? scale : 1.f;
                cl = col & 1023;
            } else {
                bp = b0p; scl = scale; cl = col;
            }
            float bb0 = bp[cl], bb1 = bp[cl + 1];
            float v0 = (acc[i][j][0] + bb0) * scl;
            float v1 = (acc[i][j][1] + bb1) * scl;
            float v2 = (acc[i][j][2] + bb0) * scl;
            float v3 = (acc[i][j][3] + bb1) * scl;
            if (relu) {
                v0 = fmaxf(v0, 0.f); v1 = fmaxf(v1, 0.f);
                v2 = fmaxf(v2, 0.f); v3 = fmaxf(v3, 0.f);
            }
            if (Cs) {
                uint32_t idx = shadow_idx(row, col, N);
                uint32_t h01, l01, h23, l23;
                split2(v0, v1, h01, l01);
                split2(v2, v3, h23, l23);
                Cs[idx]       = h01;
                Cs[idx + 1]   = h23;
                Cs[idx + 128] = l01;
                Cs[idx + 129] = l23;
            } else {
                *(float2*)(Cf + (size_t)row * ldc + col)       = make_float2(v0, v1);
                *(float2*)(Cf + (size_t)(row + 8) * ldc + col) = make_float2(v2, v3);
            }
        }
    }
}

// ================= attention: reads fused QKV (stride 3072), writes SPLIT output ============
#define AKS 0
#define AVS (256*66)
#define AQ  (2*256*66)
#define AP  (AQ + 8*4*64)
#define ATTN_SMEM ((AP + 8*256*4) * 4)

__global__ __launch_bounds__(256, 1) void attn_kernel(
    const float* __restrict__ QKV, uint32_t* __restrict__ OutS, int causal)
{
    extern __shared__ float sm[];
    float* Ks = sm + AKS;
    float* Vs = sm + AVS;
    float* qs = sm + AQ;
    float* ps = sm + AP;

    int tid = threadIdx.x;
    int lane = tid & 31, wrp = tid >> 5;
    int n = blockIdx.x & (Nb - 1);
    int h = blockIdx.x >> 4;
    int bc = h * HDh;

    for (int i = tid; i < 4096; i += 256) {
        int s = i >> 4;
        int d4 = (i & 15) * 4;
        const float* rowp = QKV + (size_t)(s * Nb + n) * QKVS;
        float4 kv = *(const float4*)(rowp + 1024 + bc + d4);
        float4 vv = *(const float4*)(rowp + 2048 + bc + d4);
        float* kd = &Ks[s * 66 + d4];
        float* vd = &Vs[s * 66 + d4];
        kd[0] = kv.x; kd[1] = kv.y; kd[2] = kv.z; kd[3] = kv.w;
        vd[0] = vv.x; vd[1] = vv.y; vd[2] = vv.z; vd[3] = vv.w;
    }
    __syncthreads();

    float* qw = qs + wrp * 4 * 64;
    float* pw = ps + wrp * 256 * 4;

    for (int it = 0; it < 8; it++) {
        int tbase = (it * 8 + wrp) * 4;
#pragma unroll
        for (int tt = 0; tt < 4; tt++) {
            float2 q2 = *(const float2*)(QKV + (size_t)((tbase + tt) * Nb + n) * QKVS + bc + 2 * lane);
            *(float2*)&qw[tt * 64 + 2 * lane] = q2;
        }
        __syncwarp();

        float sc[4][8];
#pragma unroll
        for (int tt = 0; tt < 4; tt++)
#pragma unroll
            for (int j = 0; j < 8; j++) sc[tt][j] = 0.f;

        for (int d2 = 0; d2 < 32; d2++) {
            float2 q2[4];
#pragma unroll
            for (int tt = 0; tt < 4; tt++) q2[tt] = *(const float2*)&qw[tt * 64 + 2 * d2];
#pragma unroll
            for (int j = 0; j < 8; j++) {
                float2 k2 = *(const float2*)&Ks[(j * 32 + lane) * 66 + 2 * d2];
#pragma unroll
                for (int tt = 0; tt < 4; tt++)
                    sc[tt][j] += q2[tt].x * k2.x + q2[tt].y * k2.y;
            }
        }

        float denom[4];
#pragma unroll
        for (int tt = 0; tt < 4; tt++) {
            int t = tbase + tt;
            if (causal) {
#pragma unroll
                for (int j = 0; j < 8; j++)
                    if (j * 32 + lane > t) sc[tt][j] = -1e9f;
            }
            float m = sc[tt][0];
#pragma unroll
            for (int j = 1; j < 8; j++) m = fmaxf(m, sc[tt][j]);
#pragma unroll
            for (int off = 16; off; off >>= 1) m = fmaxf(m, __shfl_xor_sync(0xffffffffu, m, off));
            float sum = 0.f;
#pragma unroll
            for (int j = 0; j < 8; j++) {
                float e = __expf(sc[tt][j] - m);
                sc[tt][j] = e;
                sum += e;
            }
#pragma unroll
            for (int off = 16; off; off >>= 1) sum += __shfl_xor_sync(0xffffffffu, sum, off);
            denom[tt] = sum;
#pragma unroll
            for (int j = 0; j < 8; j++) pw[(j * 32 + lane) * 4 + tt] = sc[tt][j];
        }
        __syncwarp();

        float2 acc[4];
#pragma unroll
        for (int tt = 0; tt < 4; tt++) acc[tt] = make_float2(0.f, 0.f);
#pragma unroll 4
        for (int s = 0; s < 256; s++) {
            float2 v2 = *(const float2*)&Vs[s * 66 + 2 * lane];
            float4 p4 = *(const float4*)&pw[s * 4];
            acc[0].x += p4.x * v2.x; acc[0].y += p4.x * v2.y;
            acc[1].x += p4.y * v2.x; acc[1].y += p4.y * v2.y;
            acc[2].x += p4.z * v2.x; acc[2].y += p4.z * v2.y;
            acc[3].x += p4.w * v2.x; acc[3].y += p4.w * v2.y;
        }
        int kcol = bc + 2 * lane;
#pragma unroll
        for (int tt = 0; tt < 4; tt++) {
            float inv = 1.f / denom[tt];
            uint32_t hi, lo;
            split2(acc[tt].x * inv, acc[tt].y * inv, hi, lo);
            uint32_t idx = shadow_idx((tbase + tt) * Nb + n, kcol, Dm);
            OutS[idx]       = hi;
            OutS[idx + 128] = lo;
        }
        __syncwarp();
    }
}

// ---------------- LayerNorm (+ residual) with optional split shadow output ----------------
__global__ void ln_kernel(const float* __restrict__ a, const float* __restrict__ r,
                          const float* __restrict__ g, const float* __restrict__ b,
                          float* __restrict__ out, uint32_t* __restrict__ sh)
{
    int row = blockIdx.x, tid = threadIdx.x;
    const float* ar = a + (size_t)row * Dm;
    const float* rr = r ? r + (size_t)row * Dm : nullptr;
    int e0 = 2 * tid;
    int e1 = 512 + 2 * tid;
    float2 p0 = *(const float2*)(ar + e0);
    float2 p1 = *(const float2*)(ar + e1);
    if (rr) {
        float2 r0 = *(const float2*)(rr + e0);
        float2 r1 = *(const float2*)(rr + e1);
        p0.x += r0.x; p0.y += r0.y;
        p1.x += r1.x; p1.y += r1.y;
    }
    float s = p0.x + p0.y + p1.x + p1.y;
    float s2 = p0.x * p0.x + p0.y * p0.y + p1.x * p1.x + p1.y * p1.y;
#pragma unroll
    for (int off = 16; off; off >>= 1) {
        s  += __shfl_down_sync(0xffffffffu, s, off);
        s2 += __shfl_down_sync(0xffffffffu, s2, off);
    }
    __shared__ float ws[8], ws2[8];
    __shared__ float mean_s, rstd_s;
    int w = tid >> 5, lane = tid & 31;
    if (!lane) { ws[w] = s; ws2[w] = s2; }
    __syncthreads();
    if (tid == 0) {
        float S = 0.f, S2 = 0.f;
        for (int i = 0; i < 8; i++) { S += ws[i]; S2 += ws2[i]; }
        float mean = S / Dm;
        float var = S2 / Dm - mean * mean;
        mean_s = mean;
        rstd_s = rsqrtf(var + 1e-5f);
    }
    __syncthreads();
    float mean = mean_s, rstd = rstd_s;
    float o00 = (p0.x - mean) * rstd * g[e0]     + b[e0];
    float o01 = (p0.y - mean) * rstd * g[e0 + 1] + b[e0 + 1];
    float o10 = (p1.x - mean) * rstd * g[e1]     + b[e1];
    float o11 = (p1.y - mean) * rstd * g[e1 + 1] + b[e1 + 1];
    *(float2*)(out + (size_t)row * Dm + e0) = make_float2(o00, o01);
    *(float2*)(out + (size_t)row * Dm + e1) = make_float2(o10, o11);
    if (sh) {
        uint32_t hi, lo;
        split2(o00, o01, hi, lo);
        uint32_t i0 = shadow_idx(row, e0, Dm);
        sh[i0] = hi; sh[i0 + 128] = lo;
        split2(o10, o11, hi, lo);
        uint32_t i1 = shadow_idx(row, e1, Dm);
        sh[i1] = hi; sh[i1 + 128] = lo;
    }
}

// ---------------- host ----------------
extern "C" void kernel_launch(void* const* d_in, const int* in_sizes, int n_in,
                              void* d_out, int out_size)
{
    const float* tgt    = (const float*)d_in[0];
    const float* memory = (const float*)d_in[1];

    bool grouped = (in_sizes[3] == Ltot * Dm * Dm);
    const float *sa_w[4], *sa_b[4], *ca_w[4], *ca_b[4];
    if (grouped) {
        for (int j = 0; j < 4; j++) {
            sa_w[j] = (const float*)d_in[2 + j];
            sa_b[j] = (const float*)d_in[6 + j];
            ca_w[j] = (const float*)d_in[10 + j];
            ca_b[j] = (const float*)d_in[14 + j];
        }
    } else {
        for (int j = 0; j < 4; j++) {
            sa_w[j] = (const float*)d_in[2 + 2 * j];
            sa_b[j] = (const float*)d_in[3 + 2 * j];
            ca_w[j] = (const float*)d_in[10 + 2 * j];
            ca_b[j] = (const float*)d_in[11 + 2 * j];
        }
    }
    const float* w1   = (const float*)d_in[18];
    const float* b1   = (const float*)d_in[19];
    const float* w2   = (const float*)d_in[20];
    const float* b2   = (const float*)d_in[21];
    const float* ln1g = (const float*)d_in[22];
    const float* ln1b = (const float*)d_in[23];
    const float* ln2g = (const float*)d_in[24];
    const float* ln2b = (const float*)d_in[25];
    const float* ln3g = (const float*)d_in[26];
    const float* ln3b = (const float*)d_in[27];
    const float* lnfg = (const float*)d_in[28];
    const float* lnfb = (const float*)d_in[29];

    float* arena;
    cudaGetSymbolAddress((void**)&arena, g_arena);
    float* px   = arena + OFF_X;
    float* pqkv = arena + OFF_QKV;
    float* pp   = arena + OFF_P;
    uint32_t* pax = (uint32_t*)arena + OFF_ASHX;
    uint32_t* pam = (uint32_t*)arena + OFF_ASHM;
    uint32_t* pah = (uint32_t*)arena + OFF_ASHH;
    uint32_t* pws = (uint32_t*)arena + OFF_WSH;

    cudaFuncSetAttribute(gemm_bf3, cudaFuncAttributeMaxDynamicSharedMemorySize, GEMM_SMEM);
    cudaFuncSetAttribute(attn_kernel, cudaFuncAttributeMaxDynamicSharedMemorySize, ATTN_SMEM);

    const uint32_t WS_SA = 0;              // slots 0..3 contiguous (QKV fusion uses 0..2)
    const uint32_t WS_CA = 4u*1024*1024;   // slots 0..3 (KV fusion uses 1..2)
    const uint32_t WS_W1 = 8u*1024*1024;
    const uint32_t WS_W2 = 12u*1024*1024;
    const size_t SZ_DD = (size_t)Dm * Dm;

    auto wsplit = [&](const float* W, uint32_t* out, int Nn, int K) {
        int total = Nn * (K >> 1);
        wsplit_kernel<<<(total + 255) / 256, 256>>>(W, out, Nn, K);
    };
    auto gemm = [&](const uint32_t* Ash, const uint32_t* Bsh,
                    const float* b0, const float* b1b, const float* b2b, int seg3,
                    float* Cf, uint32_t* Cs, int M, int N, int ldc, int K,
                    float scale, int relu) {
        dim3 grid(N / 256, M / 128);
        gemm_bf3<<<grid, 512, GEMM_SMEM>>>(Ash, Bsh, b0, b1b, b2b, seg3, Cf, Cs,
                                           M, N, ldc, K, scale, relu);
    };

    // launch 1: memory shadow; launch 2: x copy+split
    {
        int total = TOK * (Dm >> 1);
        asplit_kernel<<<(total + 255) / 256, 256>>>(memory, pam, TOK, Dm);
    }
    {
        int n4 = TOK * Dm / 4;
        copy_split_kernel<<<(n4 + 255) / 256, 256>>>((float4*)px, (const float4*)tgt, pax, n4);
    }

    const float qscale = 0.125f;  // 64^-0.5

    for (int l = 0; l < Ltot; l++) {
        size_t bo = (size_t)l * Dm;

        // ---- self-attention (causal) ----
        // launches 3,4,5 = wsplit; launch 6 = fused QKV gemm (ncu -s 5 -c 1 captures it)
        wsplit(sa_w[0] + (size_t)l * SZ_DD, pws + WS_SA + 0 * SZ_DD, Dm, Dm);
        wsplit(sa_w[1] + (size_t)l * SZ_DD, pws + WS_SA + 1 * SZ_DD, Dm, Dm);
        wsplit(sa_w[2] + (size_t)l * SZ_DD, pws + WS_SA + 2 * SZ_DD, Dm, Dm);
        gemm(pax, pws + WS_SA, sa_b[0] + bo, sa_b[1] + bo, sa_b[2] + bo, 1,
             pqkv, nullptr, TOK, 3072, QKVS, Dm, qscale, 0);
        attn_kernel<<<Nb * 16, 256, ATTN_SMEM>>>(pqkv, pax, 1);
        wsplit(sa_w[3] + (size_t)l * SZ_DD, pws + WS_SA + 3 * SZ_DD, Dm, Dm);
        gemm(pax, pws + WS_SA + 3 * SZ_DD, sa_b[3] + bo, nullptr, nullptr, 0,
             pp, nullptr, TOK, Dm, Dm, Dm, 1.f, 0);
        ln_kernel<<<TOK, 256>>>(px, pp, ln1g + bo, ln1b + bo, px, pax);

        // ---- cross-attention ----
        wsplit(ca_w[0] + (size_t)l * SZ_DD, pws + WS_CA + 0 * SZ_DD, Dm, Dm);
        wsplit(ca_w[1] + (size_t)l * SZ_DD, pws + WS_CA + 1 * SZ_DD, Dm, Dm);
        wsplit(ca_w[2] + (size_t)l * SZ_DD, pws + WS_CA + 2 * SZ_DD, Dm, Dm);
        gemm(pax, pws + WS_CA, ca_b[0] + bo, nullptr, nullptr, 0,
             pqkv, nullptr, TOK, Dm, QKVS, Dm, qscale, 0);                       // Q -> cols 0..1023
        gemm(pam, pws + WS_CA + 1 * SZ_DD, ca_b[1] + bo, ca_b[2] + bo, nullptr, 1,
             pqkv + 1024, nullptr, TOK, 2048, QKVS, Dm, 1.f, 0);                 // K|V -> cols 1024..3071
        attn_kernel<<<Nb * 16, 256, ATTN_SMEM>>>(pqkv, pax, 0);
        wsplit(ca_w[3] + (size_t)l * SZ_DD, pws + WS_CA + 3 * SZ_DD, Dm, Dm);
        gemm(pax, pws + WS_CA + 3 * SZ_DD, ca_b[3] + bo, nullptr, nullptr, 0,
             pp, nullptr, TOK, Dm, Dm, Dm, 1.f, 0);
        ln_kernel<<<TOK, 256>>>(px, pp, ln2g + bo, ln2b + bo, px, pax);

        // ---- FFN ----
        wsplit(w1 + (size_t)l * FFd * Dm, pws + WS_W1, FFd, Dm);
        gemm(pax, pws + WS_W1, b1 + (size_t)l * FFd, nullptr, nullptr, 0,
             nullptr, pah, TOK, FFd, FFd, Dm, 1.f, 1);
        wsplit(w2 + (size_t)l * Dm * FFd, pws + WS_W2, Dm, FFd);
        gemm(pah, pws + WS_W2, b2 + bo, nullptr, nullptr, 0,
             pp, nullptr, TOK, Dm, Dm, FFd, 1.f, 0);
        ln_kernel<<<TOK, 256>>>(px, pp, ln3g + bo, ln3b + bo, px, pax);
    }

    ln_kernel<<<TOK, 256>>>(px, nullptr, lnfg, lnfb, (float*)d_out, nullptr);
}

// round 15
// speedup vs baseline: 1.0144x; 1.0007x over previous
#include <cuda_runtime.h>
#include <cuda_bf16.h>
#include <math.h>
#include <stdint.h>

#define Ltot 4
#define Dm   1024
#define FFd  4096
#define Tt   256
#define Ss   256
#define Nb   16
#define HDh  64
#define TOK  (Tt*Nb)   // 4096 tokens

// ---------------- single scratch arena (256MB) ----------------
//   X    0..4M     activations f32
//   QKV  4M..16M   fused q|k|v f32, row stride 3072
//   P    20M..24M  pre-LN gemm output f32
//   ASHH 4M..20M   h1 shadow overlay (16M words), FFN only (QKV dead then)
//   ASHX 40M..44M  activation shadow
//   ASHM 44M..48M  memory shadow
//   WSH  48M..64M  per-layer weight shadows
__device__ float g_arena[64u * 1024 * 1024];

#define OFF_X    (0)
#define OFF_QKV  (4u*1024*1024)
#define OFF_P    (20u*1024*1024)
#define OFF_ASHX (40u*1024*1024)
#define OFF_ASHM (44u*1024*1024)
#define OFF_WSH  (48u*1024*1024)
#define OFF_ASHH OFF_QKV
#define QKVS 3072

// ---------------- small helpers ----------------
__device__ __forceinline__ uint32_t smem_to_u32(const void* p) {
    uint32_t a;
    asm("{ .reg .u64 t; cvta.to.shared.u64 t, %1; cvt.u32.u64 %0, t; }" : "=r"(a) : "l"(p));
    return a;
}
__device__ __forceinline__ uint32_t pack_bf16(float x, float y) {
    __nv_bfloat162 t; t.x = __float2bfloat16(x); t.y = __float2bfloat16(y);
    return *reinterpret_cast<uint32_t*>(&t);
}
__device__ __forceinline__ void split2(float v0, float v1, uint32_t& hi, uint32_t& lo) {
    __nv_bfloat16 h0 = __float2bfloat16(v0);
    __nv_bfloat16 h1 = __float2bfloat16(v1);
    float r0 = v0 - __bfloat162float(h0);
    float r1 = v1 - __bfloat162float(h1);
    __nv_bfloat162 t; t.x = h0; t.y = h1;
    hi = *reinterpret_cast<uint32_t*>(&t);
    lo = pack_bf16(r0, r1);
}
// A-side shadow layout (validated R7..R12)
__device__ __forceinline__ uint32_t shadow_idx(int row, int k, int Ktot) {
    int tile = (row >> 7) * (Ktot >> 5) + (k >> 5);
    int sub = row & 127;
    int ib = sub >> 4, r0 = (sub >> 3) & 1, gg = sub & 7;
    int kk = k & 31;
    int ks = kk >> 4, r1 = (kk & 15) >> 3, tg = (kk & 7) >> 1;
    return (uint32_t)tile * 4096u + (uint32_t)(((((ib * 2 + ks) * 2) * 32) + (gg * 4 + tg)) * 4 + (r1 * 2 + r0));
}
__device__ __forceinline__ void cp16(uint32_t saddr, const void* g) {
    asm volatile("cp.async.cg.shared.global [%0], [%1], 16;" :: "r"(saddr), "l"(g));
}
#define CP_COMMIT() asm volatile("cp.async.commit_group;" ::: "memory")
#define CP_WAIT1()  asm volatile("cp.async.wait_group 1;" ::: "memory")

__device__ __forceinline__ void lds128(uint32_t* r, uint32_t a) {
    asm volatile("ld.shared.v4.b32 {%0,%1,%2,%3},[%4];"
                 : "=r"(r[0]), "=r"(r[1]), "=r"(r[2]), "=r"(r[3]) : "r"(a));
}
__device__ __forceinline__ void mma16(float* c, const uint32_t* a, const uint32_t* b) {
    asm volatile(
        "mma.sync.aligned.m16n8k16.row.col.f32.bf16.bf16.f32 "
        "{%0,%1,%2,%3},{%4,%5,%6,%7},{%8,%9},{%0,%1,%2,%3};\n"
        : "+f"(c[0]), "+f"(c[1]), "+f"(c[2]), "+f"(c[3])
        : "r"(a[0]), "r"(a[1]), "r"(a[2]), "r"(a[3]), "r"(b[0]), "r"(b[1]));
}

// ---------------- copy + split ----------------
__global__ void copy_split_kernel(float4* __restrict__ dst, const float4* __restrict__ src,
                                  uint32_t* __restrict__ sh, int n4) {
    int i = blockIdx.x * blockDim.x + threadIdx.x;
    if (i >= n4) return;
    float4 v = src[i];
    dst[i] = v;
    int row = (i * 4) >> 10;
    int k   = (i * 4) & 1023;
    uint32_t h0, l0, h1, l1;
    split2(v.x, v.y, h0, l0);
    split2(v.z, v.w, h1, l1);
    uint32_t i0 = shadow_idx(row, k, Dm);
    uint32_t i1 = shadow_idx(row, k + 2, Dm);
    sh[i0] = h0; sh[i0 + 128] = l0;
    sh[i1] = h1; sh[i1 + 128] = l1;
}

// ================= weight split: jb-paired fragment-major (validated R11) =================
// word = tile*8192 + ((((jb>>1)*2+ks)*2 + part)*32 + lane)*4 + (jb&1)*2 + r ; lo at +128 words.
// Contiguity: a 1024-wide weight's shadow = 4 nt-tiles = 1M words, so adjacent weight slots
// concatenate into a valid wider-N shadow (used by the fused QKV / KV gemms).
__global__ void wsplit_kernel(const float* __restrict__ W, uint32_t* __restrict__ out, int Nn, int K) {
    int tid = blockIdx.x * blockDim.x + threadIdx.x;
    int total = Nn * (K >> 1);
    if (tid >= total) return;
    int r    = tid & 1;
    int lane = (tid >> 1) & 31;
    int ks   = (tid >> 6) & 1;
    int jb   = (tid >> 7) & 31;
    int tile = tid >> 12;
    int KT = K >> 5;
    int kt = tile % KT, nt = tile / KT;
    int g = lane >> 2, tg = lane & 3;
    int n = nt * 256 + jb * 8 + g;
    int k = kt * 32 + ks * 16 + 2 * tg + r * 8;
    float v0 = W[(size_t)n * K + k];
    float v1 = W[(size_t)n * K + k + 1];
    uint32_t hi, lo;
    split2(v0, v1, hi, lo);
    uint32_t base = (uint32_t)tile * 8192u +
                    (uint32_t)(((((jb >> 1) * 2 + ks) * 2) * 32 + lane) * 4 + (jb & 1) * 2 + r);
    out[base]       = hi;   // part 0
    out[base + 128] = lo;   // part 1
}

// ================= activation split (A-side; only `memory`, once) =================
__global__ void asplit_kernel(const float* __restrict__ A, uint32_t* __restrict__ out, int M, int K) {
    int tid = blockIdx.x * blockDim.x + threadIdx.x;
    int total = M * (K >> 1);
    if (tid >= total) return;
    int r4   = tid & 3;
    int lane = (tid >> 2) & 31;
    int ks   = (tid >> 7) & 1;
    int ib   = (tid >> 8) & 7;
    int tile = tid >> 11;
    int KT = K >> 5;
    int kt = tile % KT, mt = tile / KT;
    int g = lane >> 2, tg = lane & 3;
    int row = mt * 128 + ib * 16 + g + (r4 & 1) * 8;
    int k   = kt * 32 + ks * 16 + 2 * tg + (r4 >> 1) * 8;
    float v0 = A[(size_t)row * K + k];
    float v1 = A[(size_t)row * K + k + 1];
    uint32_t hi, lo;
    split2(v0, v1, hi, lo);
    uint32_t base = (uint32_t)tile * 4096u + ((((ib * 2 + ks) * 2) * 32 + lane) * 4 + r4);
    out[base]       = hi;
    out[base + 128] = lo;
}

// ================= GEMM: R11-exact mainloop; epilogue gains ldc + segmented bias ============
// C[M,N] (row stride ldc) = op((A@B^T + bias)*scale). seg3: bias/scale per 1024-col segment
// (segment 0 gets `scale`, others 1.0; bias pointers b0/b1/b2 per segment).
#define STAGE_BYTES 49152
#define GEMM_SMEM   (3 * STAGE_BYTES)

__global__ __launch_bounds__(512, 1) void gemm_bf3(
    const uint32_t* __restrict__ Ash, const uint32_t* __restrict__ Bsh,
    const float* __restrict__ b0p, const float* __restrict__ b1p, const float* __restrict__ b2p,
    int seg3, float* __restrict__ Cf, uint32_t* __restrict__ Cs,
    int M, int N, int ldc, int K, float scale, int relu)
{
    extern __shared__ char smem[];
    uint32_t sbase = smem_to_u32(smem);
    int tid = threadIdx.x, lane = tid & 31, wid = tid >> 5;
    int wm = (wid & 3) * 32;         // 4 M-warps
    int wn = (wid >> 2) * 64;        // 4 N-warps
    int g = lane >> 2, tg = lane & 3;
    int KT = K >> 5;
    int nt = blockIdx.x, mt = blockIdx.y;
    const uint32_t* Asrc = Ash + (size_t)mt * KT * 4096;
    const uint32_t* Bsrc = Bsh + (size_t)nt * KT * 8192;

    float acc[2][8][4];
#pragma unroll
    for (int i = 0; i < 2; i++)
#pragma unroll
        for (int j = 0; j < 8; j++)
#pragma unroll
            for (int e = 0; e < 4; e++) acc[i][j][e] = 0.f;

    auto issue = [&](int s) {
        uint32_t st = sbase + (uint32_t)(s % 3) * STAGE_BYTES;
        const char* ga = (const char*)(Asrc + (size_t)s * 4096) + tid * 32;
#pragma unroll
        for (int c = 0; c < 2; c++) cp16(st + tid * 32 + c * 16, ga + c * 16);
        const char* gb = (const char*)(Bsrc + (size_t)s * 8192) + tid * 64;
#pragma unroll
        for (int c = 0; c < 4; c++) cp16(st + 16384 + tid * 64 + c * 16, gb + c * 16);
    };

    issue(0); CP_COMMIT();
    if (KT > 1) issue(1);
    CP_COMMIT();

    for (int s = 0; s < KT; s++) {
        CP_WAIT1();
        __syncthreads();
        uint32_t sA = sbase + (uint32_t)(s % 3) * STAGE_BYTES;
        uint32_t sB = sA + 16384;
#pragma unroll
        for (int ks = 0; ks < 2; ks++) {
            uint32_t aH[2][4], aL[2][4];
#pragma unroll
            for (int i = 0; i < 2; i++) {
                int ib = (wm >> 4) + i;
                uint32_t off = sA + (uint32_t)((((ib * 2 + ks) * 2) * 32 + lane) * 16);
                lds128(aH[i], off);
                lds128(aL[i], off + 512);
            }
#pragma unroll
            for (int jh = 0; jh < 2; jh++) {
                uint32_t bH[4][2], bL[4][2];
#pragma unroll
                for (int p = 0; p < 2; p++) {
                    int jp = (wn >> 4) + jh * 2 + p;
                    uint32_t boff = sB + (uint32_t)((((jp * 2 + ks) * 2) * 32 + lane) * 16);
                    uint32_t th[4], tl[4];
                    lds128(th, boff);
                    lds128(tl, boff + 512);
                    bH[p * 2][0]     = th[0]; bH[p * 2][1]     = th[1];
                    bH[p * 2 + 1][0] = th[2]; bH[p * 2 + 1][1] = th[3];
                    bL[p * 2][0]     = tl[0]; bL[p * 2][1]     = tl[1];
                    bL[p * 2 + 1][0] = tl[2]; bL[p * 2 + 1][1] = tl[3];
                }
#pragma unroll
                for (int i = 0; i < 2; i++)
#pragma unroll
                    for (int j = 0; j < 4; j++) {
                        float* c = acc[i][jh * 4 + j];
                        mma16(c, aH[i], bH[j]);
                        mma16(c, aH[i], bL[j]);
                        mma16(c, aL[i], bH[j]);
                    }
            }
        }
        __syncthreads();
        if (s + 2 < KT) issue(s + 2);
        CP_COMMIT();
    }

    // epilogue
#pragma unroll
    for (int i = 0; i < 2; i++) {
#pragma unroll
        for (int j = 0; j < 8; j++) {
            int row = mt * 128 + wm + i * 16 + g;
            int col = nt * 256 + wn + j * 8 + tg * 2;
            const float* bp;
            float scl;
            int cl;
            if (seg3) {
                int sgi = col >> 10;
                bp = (sgi == 0) ? b0p : ((sgi == 1) ? b1p : b2p);
                scl = (sgi == 0) ? scale : 1.f;
                cl = col & 1023;
            } else {
                bp = b0p; scl = scale; cl = col;
            }
            float bb0 = bp[cl], bb1 = bp[cl + 1];
            float v0 = (acc[i][j][0] + bb0) * scl;
            float v1 = (acc[i][j][1] + bb1) * scl;
            float v2 = (acc[i][j][2] + bb0) * scl;
            float v3 = (acc[i][j][3] + bb1) * scl;
            if (relu) {
                v0 = fmaxf(v0, 0.f); v1 = fmaxf(v1, 0.f);
                v2 = fmaxf(v2, 0.f); v3 = fmaxf(v3, 0.f);
            }
            if (Cs) {
                uint32_t idx = shadow_idx(row, col, N);
                uint32_t h01, l01, h23, l23;
                split2(v0, v1, h01, l01);
                split2(v2, v3, h23, l23);
                Cs[idx]       = h01;
                Cs[idx + 1]   = h23;
                Cs[idx + 128] = l01;
                Cs[idx + 129] = l23;
            } else {
                *(float2*)(Cf + (size_t)row * ldc + col)       = make_float2(v0, v1);
                *(float2*)(Cf + (size_t)(row + 8) * ldc + col) = make_float2(v2, v3);
            }
        }
    }
}

// ================= attention: reads fused QKV (stride 3072), writes SPLIT output ============
#define AKS 0
#define AVS (256*66)
#define AQ  (2*256*66)
#define AP  (AQ + 8*4*64)
#define ATTN_SMEM ((AP + 8*256*4) * 4)

__global__ __launch_bounds__(256, 1) void attn_kernel(
    const float* __restrict__ QKV, uint32_t* __restrict__ OutS, int causal)
{
    extern __shared__ float sm[];
    float* Ks = sm + AKS;
    float* Vs = sm + AVS;
    float* qs = sm + AQ;
    float* ps = sm + AP;

    int tid = threadIdx.x;
    int lane = tid & 31, wrp = tid >> 5;
    int n = blockIdx.x & (Nb - 1);
    int h = blockIdx.x >> 4;
    int bc = h * HDh;

    for (int i = tid; i < 4096; i += 256) {
        int s = i >> 4;
        int d4 = (i & 15) * 4;
        const float* rowp = QKV + (size_t)(s * Nb + n) * QKVS;
        float4 kv = *(const float4*)(rowp + 1024 + bc + d4);
        float4 vv = *(const float4*)(rowp + 2048 + bc + d4);
        float* kd = &Ks[s * 66 + d4];
        float* vd = &Vs[s * 66 + d4];
        kd[0] = kv.x; kd[1] = kv.y; kd[2] = kv.z; kd[3] = kv.w;
        vd[0] = vv.x; vd[1] = vv.y; vd[2] = vv.z; vd[3] = vv.w;
    }
    __syncthreads();

    float* qw = qs + wrp * 4 * 64;
    float* pw = ps + wrp * 256 * 4;

    for (int it = 0; it < 8; it++) {
        int tbase = (it * 8 + wrp) * 4;
#pragma unroll
        for (int tt = 0; tt < 4; tt++) {
            float2 q2 = *(const float2*)(QKV + (size_t)((tbase + tt) * Nb + n) * QKVS + bc + 2 * lane);
            *(float2*)&qw[tt * 64 + 2 * lane] = q2;
        }
        __syncwarp();

        float sc[4][8];
#pragma unroll
        for (int tt = 0; tt < 4; tt++)
#pragma unroll
            for (int j = 0; j < 8; j++) sc[tt][j] = 0.f;

        for (int d2 = 0; d2 < 32; d2++) {
            float2 q2[4];
#pragma unroll
            for (int tt = 0; tt < 4; tt++) q2[tt] = *(const float2*)&qw[tt * 64 + 2 * d2];
#pragma unroll
            for (int j = 0; j < 8; j++) {
                float2 k2 = *(const float2*)&Ks[(j * 32 + lane) * 66 + 2 * d2];
#pragma unroll
                for (int tt = 0; tt < 4; tt++)
                    sc[tt][j] += q2[tt].x * k2.x + q2[tt].y * k2.y;
            }
        }

        float denom[4];
#pragma unroll
        for (int tt = 0; tt < 4; tt++) {
            int t = tbase + tt;
            if (causal) {
#pragma unroll
                for (int j = 0; j < 8; j++)
                    if (j * 32 + lane > t) sc[tt][j] = -1e9f;
            }
            float m = sc[tt][0];
#pragma unroll
            for (int j = 1; j < 8; j++) m = fmaxf(m, sc[tt][j]);
#pragma unroll
            for (int off = 16; off; off >>= 1) m = fmaxf(m, __shfl_xor_sync(0xffffffffu, m, off));
            float sum = 0.f;
#pragma unroll
            for (int j = 0; j < 8; j++) {
                float e = __expf(sc[tt][j] - m);
                sc[tt][j] = e;
                sum += e;
            }
#pragma unroll
            for (int off = 16; off; off >>= 1) sum += __shfl_xor_sync(0xffffffffu, sum, off);
            denom[tt] = sum;
#pragma unroll
            for (int j = 0; j < 8; j++) pw[(j * 32 + lane) * 4 + tt] = sc[tt][j];
        }
        __syncwarp();

        float2 acc[4];
#pragma unroll
        for (int tt = 0; tt < 4; tt++) acc[tt] = make_float2(0.f, 0.f);
#pragma unroll 4
        for (int s = 0; s < 256; s++) {
            float2 v2 = *(const float2*)&Vs[s * 66 + 2 * lane];
            float4 p4 = *(const float4*)&pw[s * 4];
            acc[0].x += p4.x * v2.x; acc[0].y += p4.x * v2.y;
            acc[1].x += p4.y * v2.x; acc[1].y += p4.y * v2.y;
            acc[2].x += p4.z * v2.x; acc[2].y += p4.z * v2.y;
            acc[3].x += p4.w * v2.x; acc[3].y += p4.w * v2.y;
        }
        int kcol = bc + 2 * lane;
#pragma unroll
        for (int tt = 0; tt < 4; tt++) {
            float inv = 1.f / denom[tt];
            uint32_t hi, lo;
            split2(acc[tt].x * inv, acc[tt].y * inv, hi, lo);
            uint32_t idx = shadow_idx((tbase + tt) * Nb + n, kcol, Dm);
            OutS[idx]       = hi;
            OutS[idx + 128] = lo;
        }
        __syncwarp();
    }
}

// ---------------- LayerNorm (+ residual) with optional split shadow output ----------------
__global__ void ln_kernel(const float* __restrict__ a, const float* __restrict__ r,
                          const float* __restrict__ g, const float* __restrict__ b,
                          float* __restrict__ out, uint32_t* __restrict__ sh)
{
    int row = blockIdx.x, tid = threadIdx.x;
    const float* ar = a + (size_t)row * Dm;
    const float* rr = r ? r + (size_t)row * Dm : nullptr;
    int e0 = 2 * tid;
    int e1 = 512 + 2 * tid;
    float2 p0 = *(const float2*)(ar + e0);
    float2 p1 = *(const float2*)(ar + e1);
    if (rr) {
        float2 r0 = *(const float2*)(rr + e0);
        float2 r1 = *(const float2*)(rr + e1);
        p0.x += r0.x; p0.y += r0.y;
        p1.x += r1.x; p1.y += r1.y;
    }
    float s = p0.x + p0.y + p1.x + p1.y;
    float s2 = p0.x * p0.x + p0.y * p0.y + p1.x * p1.x + p1.y * p1.y;
#pragma unroll
    for (int off = 16; off; off >>= 1) {
        s  += __shfl_down_sync(0xffffffffu, s, off);
        s2 += __shfl_down_sync(0xffffffffu, s2, off);
    }
    __shared__ float ws[8], ws2[8];
    __shared__ float mean_s, rstd_s;
    int w = tid >> 5, lane = tid & 31;
    if (!lane) { ws[w] = s; ws2[w] = s2; }
    __syncthreads();
    if (tid == 0) {
        float S = 0.f, S2 = 0.f;
        for (int i = 0; i < 8; i++) { S += ws[i]; S2 += ws2[i]; }
        float mean = S / Dm;
        float var = S2 / Dm - mean * mean;
        mean_s = mean;
        rstd_s = rsqrtf(var + 1e-5f);
    }
    __syncthreads();
    float mean = mean_s, rstd = rstd_s;
    float o00 = (p0.x - mean) * rstd * g[e0]     + b[e0];
    float o01 = (p0.y - mean) * rstd * g[e0 + 1] + b[e0 + 1];
    float o10 = (p1.x - mean) * rstd * g[e1]     + b[e1];
    float o11 = (p1.y - mean) * rstd * g[e1 + 1] + b[e1 + 1];
    *(float2*)(out + (size_t)row * Dm + e0) = make_float2(o00, o01);
    *(float2*)(out + (size_t)row * Dm + e1) = make_float2(o10, o11);
    if (sh) {
        uint32_t hi, lo;
        split2(o00, o01, hi, lo);
        uint32_t i0 = shadow_idx(row, e0, Dm);
        sh[i0] = hi; sh[i0 + 128] = lo;
        split2(o10, o11, hi, lo);
        uint32_t i1 = shadow_idx(row, e1, Dm);
        sh[i1] = hi; sh[i1 + 128] = lo;
    }
}

// ---------------- host ----------------
extern "C" void kernel_launch(void* const* d_in, const int* in_sizes, int n_in,
                              void* d_out, int out_size)
{
    const float* tgt    = (const float*)d_in[0];
    const float* memory = (const float*)d_in[1];

    bool grouped = (in_sizes[3] == Ltot * Dm * Dm);
    const float *sa_w[4], *sa_b[4], *ca_w[4], *ca_b[4];
    if (grouped) {
        for (int j = 0; j < 4; j++) {
            sa_w[j] = (const float*)d_in[2 + j];
            sa_b[j] = (const float*)d_in[6 + j];
            ca_w[j] = (const float*)d_in[10 + j];
            ca_b[j] = (const float*)d_in[14 + j];
        }
    } else {
        for (int j = 0; j < 4; j++) {
            sa_w[j] = (const float*)d_in[2 + 2 * j];
            sa_b[j] = (const float*)d_in[3 + 2 * j];
            ca_w[j] = (const float*)d_in[10 + 2 * j];
            ca_b[j] = (const float*)d_in[11 + 2 * j];
        }
    }
    const float* w1   = (const float*)d_in[18];
    const float* b1   = (const float*)d_in[19];
    const float* w2   = (const float*)d_in[20];
    const float* b2   = (const float*)d_in[21];
    const float* ln1g = (const float*)d_in[22];
    const float* ln1b = (const float*)d_in[23];
    const float* ln2g = (const float*)d_in[24];
    const float* ln2b = (const float*)d_in[25];
    const float* ln3g = (const float*)d_in[26];
    const float* ln3b = (const float*)d_in[27];
    const float* lnfg = (const float*)d_in[28];
    const float* lnfb = (const float*)d_in[29];

    float* arena;
    cudaGetSymbolAddress((void**)&arena, g_arena);
    float* px   = arena + OFF_X;
    float* pqkv = arena + OFF_QKV;
    float* pp   = arena + OFF_P;
    uint32_t* pax = (uint32_t*)arena + OFF_ASHX;
    uint32_t* pam = (uint32_t*)arena + OFF_ASHM;
    uint32_t* pah = (uint32_t*)arena + OFF_ASHH;
    uint32_t* pws = (uint32_t*)arena + OFF_WSH;

    cudaFuncSetAttribute(gemm_bf3, cudaFuncAttributeMaxDynamicSharedMemorySize, GEMM_SMEM);
    cudaFuncSetAttribute(attn_kernel, cudaFuncAttributeMaxDynamicSharedMemorySize, ATTN_SMEM);

    const uint32_t WS_SA = 0;              // slots 0..3 contiguous (QKV fusion uses 0..2)
    const uint32_t WS_CA = 4u*1024*1024;   // slots 0..3 (KV fusion uses 1..2)
    const uint32_t WS_W1 = 8u*1024*1024;
    const uint32_t WS_W2 = 12u*1024*1024;
    const size_t SZ_DD = (size_t)Dm * Dm;

    auto wsplit = [&](const float* W, uint32_t* out, int Nn, int K) {
        int total = Nn * (K >> 1);
        wsplit_kernel<<<(total + 255) / 256, 256>>>(W, out, Nn, K);
    };
    auto gemm = [&](const uint32_t* Ash, const uint32_t* Bsh,
                    const float* b0, const float* b1b, const float* b2b, int seg3,
                    float* Cf, uint32_t* Cs, int M, int N, int ldc, int K,
                    float scale, int relu) {
        dim3 grid(N / 256, M / 128);
        gemm_bf3<<<grid, 512, GEMM_SMEM>>>(Ash, Bsh, b0, b1b, b2b, seg3, Cf, Cs,
                                           M, N, ldc, K, scale, relu);
    };

    // launch 1: memory shadow; launch 2: x copy+split
    {
        int total = TOK * (Dm >> 1);
        asplit_kernel<<<(total + 255) / 256, 256>>>(memory, pam, TOK, Dm);
    }
    {
        int n4 = TOK * Dm / 4;
        copy_split_kernel<<<(n4 + 255) / 256, 256>>>((float4*)px, (const float4*)tgt, pax, n4);
    }

    const float qscale = 0.125f;  // 64^-0.5

    for (int l = 0; l < Ltot; l++) {
        size_t bo = (size_t)l * Dm;

        // ---- self-attention (causal) ----
        // launches 3,4,5 = wsplit; launch 6 = fused QKV gemm (ncu -s 5 -c 1 captures it)
        wsplit(sa_w[0] + (size_t)l * SZ_DD, pws + WS_SA + 0 * SZ_DD, Dm, Dm);
        wsplit(sa_w[1] + (size_t)l * SZ_DD, pws + WS_SA + 1 * SZ_DD, Dm, Dm);
        wsplit(sa_w[2] + (size_t)l * SZ_DD, pws + WS_SA + 2 * SZ_DD, Dm, Dm);
        gemm(pax, pws + WS_SA, sa_b[0] + bo, sa_b[1] + bo, sa_b[2] + bo, 1,
             pqkv, nullptr, TOK, 3072, QKVS, Dm, qscale, 0);
        attn_kernel<<<Nb * 16, 256, ATTN_SMEM>>>(pqkv, pax, 1);
        wsplit(sa_w[3] + (size_t)l * SZ_DD, pws + WS_SA + 3 * SZ_DD, Dm, Dm);
        gemm(pax, pws + WS_SA + 3 * SZ_DD, sa_b[3] + bo, nullptr, nullptr, 0,
             pp, nullptr, TOK, Dm, Dm, Dm, 1.f, 0);
        ln_kernel<<<TOK, 256>>>(px, pp, ln1g + bo, ln1b + bo, px, pax);

        // ---- cross-attention ----
        wsplit(ca_w[0] + (size_t)l * SZ_DD, pws + WS_CA + 0 * SZ_DD, Dm, Dm);
        wsplit(ca_w[1] + (size_t)l * SZ_DD, pws + WS_CA + 1 * SZ_DD, Dm, Dm);
        wsplit(ca_w[2] + (size_t)l * SZ_DD, pws + WS_CA + 2 * SZ_DD, Dm, Dm);
        gemm(pax, pws + WS_CA, ca_b[0] + bo, nullptr, nullptr, 0,
             pqkv, nullptr, TOK, Dm, QKVS, Dm, qscale, 0);                       // Q -> cols 0..1023
        gemm(pam, pws + WS_CA + 1 * SZ_DD, ca_b[1] + bo, ca_b[2] + bo, nullptr, 1,
             pqkv + 1024, nullptr, TOK, 2048, QKVS, Dm, 1.f, 0);                 // K|V -> cols 1024..3071
        attn_kernel<<<Nb * 16, 256, ATTN_SMEM>>>(pqkv, pax, 0);
        wsplit(ca_w[3] + (size_t)l * SZ_DD, pws + WS_CA + 3 * SZ_DD, Dm, Dm);
        gemm(pax, pws + WS_CA + 3 * SZ_DD, ca_b[3] + bo, nullptr, nullptr, 0,
             pp, nullptr, TOK, Dm, Dm, Dm, 1.f, 0);
        ln_kernel<<<TOK, 256>>>(px, pp, ln2g + bo, ln2b + bo, px, pax);

        // ---- FFN ----
        wsplit(w1 + (size_t)l * FFd * Dm, pws + WS_W1, FFd, Dm);
        gemm(pax, pws + WS_W1, b1 + (size_t)l * FFd, nullptr, nullptr, 0,
             nullptr, pah, TOK, FFd, FFd, Dm, 1.f, 1);
        wsplit(w2 + (size_t)l * Dm * FFd, pws + WS_W2, Dm, FFd);
        gemm(pah, pws + WS_W2, b2 + bo, nullptr, nullptr, 0,
             pp, nullptr, TOK, Dm, Dm, FFd, 1.f, 0);
        ln_kernel<<<TOK, 256>>>(px, pp, ln3g + bo, ln3b + bo, px, pax);
    }

    ln_kernel<<<TOK, 256>>>(px, nullptr, lnfg, lnfb, (float*)d_out, nullptr);
}